// round 6
// baseline (speedup 1.0000x reference)
#include <cuda_runtime.h>
#include <cuda_fp16.h>
#include <cstdint>

#define E_ 11
#define B_ 1024
#define D_ 1536
#define H_ 3072
#define C_ 5242

#define BM 128
#define BN 256
#define BK 16
#define NTHREADS 256
#define MT 2

#define SAS 24                // A fp16 tile stride (halves)
#define SA_H (BM * SAS)       // 3072 halves / stage
#define FBS 264               // B fp32 staging stride (floats)
#define SBS 264               // B fp16 tile stride (halves)
#define BSTG_STAGE (16 * FBS) // floats per staging stage
#define B16_STAGE (16 * SBS)  // halves per fp16 B buffer

// ---- scratch ----
__device__ int    g_cnt[E_];
__device__ int    g_idx[E_ * B_];
__device__ __half g_h1[(size_t)B_ * H_];
__device__ __half g_h2[(size_t)B_ * H_];

// ---------------------------------------------------------------------------
__global__ void route_kernel(const float* __restrict__ mf) {
    int tid = threadIdx.x;
    if (tid < E_) g_cnt[tid] = 0;
    __syncthreads();
    float t = 1.0f - mf[tid];
    float q = t / 0.1f;               // IEEE div, matches XLA lowering
    int bin = (int)q;                 // trunc toward zero == astype(int32)
    bin = max(0, min(E_ - 1, bin));
    int pos = atomicAdd(&g_cnt[bin], 1);
    g_idx[bin * B_ + pos] = tid;
}

// ---- PTX helpers ----------------------------------------------------------
__device__ __forceinline__ void cp_async16(uint32_t s, const void* g) {
    asm volatile("cp.async.cg.shared.global [%0], [%1], 16;\n" :: "r"(s), "l"(g));
}
__device__ __forceinline__ void cp_async8(uint32_t s, const void* g, int bytes) {
    asm volatile("cp.async.ca.shared.global [%0], [%1], 8, %2;\n"
                 :: "r"(s), "l"(g), "r"(bytes));
}
__device__ __forceinline__ void cp_commit() {
    asm volatile("cp.async.commit_group;\n" ::: "memory");
}
template <int N>
__device__ __forceinline__ void cp_wait() {
    asm volatile("cp.async.wait_group %0;\n" :: "n"(N) : "memory");
}
__device__ __forceinline__ void ldsm4(uint32_t r[4], uint32_t addr) {
    asm volatile("ldmatrix.sync.aligned.m8n8.x4.shared.b16 {%0,%1,%2,%3}, [%4];"
                 : "=r"(r[0]), "=r"(r[1]), "=r"(r[2]), "=r"(r[3]) : "r"(addr));
}
__device__ __forceinline__ void ldsm4t(uint32_t r[4], uint32_t addr) {
    asm volatile("ldmatrix.sync.aligned.m8n8.x4.trans.shared.b16 {%0,%1,%2,%3}, [%4];"
                 : "=r"(r[0]), "=r"(r[1]), "=r"(r[2]), "=r"(r[3]) : "r"(addr));
}
__device__ __forceinline__ void mma_f16(float c[4], const uint32_t a[4],
                                        const uint32_t b0, const uint32_t b1) {
    asm volatile(
        "mma.sync.aligned.m16n8k16.row.col.f32.f16.f16.f32 "
        "{%0,%1,%2,%3}, {%4,%5,%6,%7}, {%8,%9}, {%0,%1,%2,%3};\n"
        : "+f"(c[0]), "+f"(c[1]), "+f"(c[2]), "+f"(c[3])
        : "r"(a[0]), "r"(a[1]), "r"(a[2]), "r"(a[3]), "r"(b0), "r"(b1));
}
__device__ __forceinline__ void lds128f(float4& v, uint32_t a) {
    asm volatile("ld.shared.v4.f32 {%0,%1,%2,%3}, [%4];"
                 : "=f"(v.x), "=f"(v.y), "=f"(v.z), "=f"(v.w) : "r"(a));
}
__device__ __forceinline__ void sts64(uint32_t a, uint32_t v0, uint32_t v1) {
    asm volatile("st.shared.v2.b32 [%0], {%1,%2};\n" :: "r"(a), "r"(v0), "r"(v1));
}
__device__ __forceinline__ void sts128(uint32_t a, const uint32_t v[4]) {
    asm volatile("st.shared.v4.b32 [%0], {%1,%2,%3,%4};\n"
                 :: "r"(a), "r"(v[0]), "r"(v[1]), "r"(v[2]), "r"(v[3]));
}
__device__ __forceinline__ uint32_t pack2(float x, float y) {
    __half2 h = __float22half2_rn(make_float2(x, y));
    return *reinterpret_cast<uint32_t*>(&h);
}
__device__ __forceinline__ float gelu_exact(float x) {
    return 0.5f * x * (1.0f + erff(x * 0.70710678118654752f));
}

// ---------------------------------------------------------------------------
// Per-bin gather GEMM: fp16 mma.sync, CTA 128x256, 8 warps (2Mx4N, 64x64).
// W fp32 -> 4-stage cp.async staging -> smem convert (1 iter ahead) -> ldsm.
// A fp16 -> 5-stage direct cp.async (A_HALF) | fp32 -> LDG+STS reg path (L1).
// ---------------------------------------------------------------------------
template <bool DO_GELU, bool A_HALF, bool OUT_HALF, bool ALIGN16>
__global__ void __launch_bounds__(NTHREADS, 1)
expert_gemm(const void* __restrict__ Av, int lda,
            const float* __restrict__ W, const float* __restrict__ bias,
            void* __restrict__ Coutv, int ldc, int K, int N)
{
    const int e = blockIdx.z;
    const int cnt = g_cnt[e];
    const int mtile = blockIdx.y;
    if (mtile * BM >= cnt) return;
    const int n0 = blockIdx.x * BN;

    const int* idxE = g_idx + e * B_;
    const float* We = W + (size_t)e * K * N;
    const float* be = bias + (size_t)e * N;

    constexpr int A_STAGES = A_HALF ? 5 : 2;
    constexpr uint32_t OFF_A = 0;
    constexpr uint32_t OFF_BSTG = A_STAGES * SA_H * 2;
    constexpr uint32_t OFF_B16 = OFF_BSTG + 4 * BSTG_STAGE * 4;

    extern __shared__ char smem_raw[];
    const uint32_t s0 = (uint32_t)__cvta_generic_to_shared(smem_raw);

    const int tid = threadIdx.x;
    const int lane = tid & 31;
    const int warp = tid >> 5;

    // ---- A: row rA, 16B chunk (tid&1) ----
    const int rA = tid >> 1;
    const int ha = tid & 1;
    int gm = mtile * BM + rA;
    int gmc = gm < cnt ? gm : cnt - 1;
    const int arow = idxE[gmc];
    const __half* a_h = (const __half*)Av + (size_t)arow * lda + 8 * ha;
    const float*  a_f = (const float*)Av  + (size_t)arow * lda + 8 * ha;
    const uint32_t a_dst0 = s0 + OFF_A + (uint32_t)((rA * SAS + 8 * ha) * 2);

    // ---- B cp.async: k-row kB, 16-float chunk base c16 ----
    const int kB = tid >> 4;
    const int c16 = (tid & 15) * 16;
    const float* b_src = We + (size_t)kB * N + n0 + c16;
    const uint32_t b_dst0 = s0 + OFF_BSTG + (uint32_t)((kB * FBS + c16) * 4);

    // ---- convert mapping: row cvR, cols cvC + 64j ----
    const int cvR = tid >> 4;
    const int cvC = (tid & 15) * 4;

    const int KT = K / BK;

    auto issue = [&](int t) {
        if (A_HALF) {
            const uint32_t ad = a_dst0 + (uint32_t)((t % 5) * SA_H * 2);
            cp_async16(ad, a_h + (size_t)t * BK);
        }
        const uint32_t bd = b_dst0 + (uint32_t)((t & 3) * BSTG_STAGE * 4);
        const float* bs = b_src + (size_t)t * BK * N;
        if (ALIGN16) {
#pragma unroll
            for (int j = 0; j < 4; j++) cp_async16(bd + j * 16, bs + 4 * j);
        } else {
#pragma unroll
            for (int j = 0; j < 8; j++) {
                int gn = n0 + c16 + 2 * j;
                const float* p = (gn < N) ? (bs + 2 * j) : We;
                cp_async8(bd + j * 8, p, (gn < N) ? 8 : 0);
            }
        }
    };

    auto convert = [&](int u) {
        const uint32_t src = s0 + OFF_BSTG + (uint32_t)((u & 3) * BSTG_STAGE * 4);
        const uint32_t dst = s0 + OFF_B16 + (uint32_t)((u & 1) * B16_STAGE * 2);
#pragma unroll
        for (int j = 0; j < 4; j++) {
            const int col = cvC + 64 * j;
            float4 v;
            lds128f(v, src + (uint32_t)((cvR * FBS + col) * 4));
            sts64(dst + (uint32_t)((cvR * SBS + col) * 2),
                  pack2(v.x, v.y), pack2(v.z, v.w));
        }
        if (!A_HALF) {   // L1: A fp32 LDG -> fp16 STS into tile (u&1)
            const float* as = a_f + (size_t)u * BK;
            float4 v0 = *reinterpret_cast<const float4*>(as);
            float4 v1 = *reinterpret_cast<const float4*>(as + 4);
            uint32_t h[4] = { pack2(v0.x, v0.y), pack2(v0.z, v0.w),
                              pack2(v1.x, v1.y), pack2(v1.z, v1.w) };
            sts128(a_dst0 + (uint32_t)((u & 1) * SA_H * 2), h);
        }
    };

    // ---- warp tiling: 2 warps along M (64), 4 along N (64) ----
    const int wm = (warp & 1) * 64;
    const int wn = (warp >> 1) * 64;
    const int g  = lane >> 2;
    const int tg = lane & 3;

    const uint32_t a_ld0 = s0 + OFF_A +
        (uint32_t)(((wm + (lane & 15)) * SAS + (lane >> 4) * 8) * 2);
    const uint32_t b_ld0 = s0 + OFF_B16 +
        (uint32_t)(((lane & 15) * SBS + wn + (lane >> 4) * 8) * 2);

    float acc[4][8][4];
#pragma unroll
    for (int mi = 0; mi < 4; mi++)
#pragma unroll
        for (int ni = 0; ni < 8; ni++)
#pragma unroll
            for (int k = 0; k < 4; k++) acc[mi][ni][k] = 0.f;

    // ---- prologue: 3 stages in flight, convert stage 0 ----
    issue(0); cp_commit();
    issue(1); cp_commit();
    issue(2); cp_commit();
    cp_wait<2>();
    __syncthreads();
    convert(0);

    for (int t = 0; t < KT; t++) {
        if (t + 3 < KT) issue(t + 3);
        cp_commit();
        cp_wait<2>();
        __syncthreads();
        if (t + 1 < KT) convert(t + 1);

        // ---- MMA on stage t ----
        const uint32_t a_ld = a_ld0 +
            (uint32_t)((A_HALF ? (t % 5) : (t & 1)) * SA_H * 2);
        const uint32_t b_ld = b_ld0 + (uint32_t)((t & 1) * B16_STAGE * 2);
        uint32_t bf[16];
#pragma unroll
        for (int q = 0; q < 4; q++) ldsm4t(bf + 4 * q, b_ld + q * 32);
#pragma unroll
        for (int mi = 0; mi < 4; mi++) {
            uint32_t af[4];
            ldsm4(af, a_ld + (uint32_t)(mi * 16 * SAS * 2));
#pragma unroll
            for (int q = 0; q < 4; q++) {
                mma_f16(acc[mi][2 * q],     af, bf[4 * q],     bf[4 * q + 1]);
                mma_f16(acc[mi][2 * q + 1], af, bf[4 * q + 2], bf[4 * q + 3]);
            }
        }
    }

    // ---- epilogue ----
#pragma unroll
    for (int mi = 0; mi < 4; mi++) {
#pragma unroll
        for (int half = 0; half < 2; half++) {
            const int m = wm + mi * 16 + g + half * 8;
            const int gmm = mtile * BM + m;
            if (gmm >= cnt) continue;
            const int orow = idxE[gmm];
#pragma unroll
            for (int ni = 0; ni < 8; ni++) {
                const int gn = n0 + wn + ni * 8 + tg * 2;
                float v0 = acc[mi][ni][half * 2 + 0];
                float v1 = acc[mi][ni][half * 2 + 1];
                if (OUT_HALF) {
                    float r0 = v0 + be[gn];
                    float r1 = v1 + be[gn + 1];
                    if (DO_GELU) { r0 = gelu_exact(r0); r1 = gelu_exact(r1); }
                    *reinterpret_cast<__half2*>((__half*)Coutv +
                        (size_t)orow * ldc + gn) = __float22half2_rn(make_float2(r0, r1));
                } else {
                    float* op = (float*)Coutv + (size_t)orow * ldc;
                    if (gn + 1 < N) {
                        float r0 = v0 + be[gn];
                        float r1 = v1 + be[gn + 1];
                        if (DO_GELU) { r0 = gelu_exact(r0); r1 = gelu_exact(r1); }
                        *reinterpret_cast<float2*>(op + gn) = make_float2(r0, r1);
                    } else if (gn < N) {
                        float r0 = v0 + be[gn];
                        if (DO_GELU) r0 = gelu_exact(r0);
                        op[gn] = r0;
                    }
                }
            }
        }
    }
}

// ---------------------------------------------------------------------------
__global__ void logsoftmax_kernel(float* __restrict__ out) {
    const int b = blockIdx.x;
    float* row = out + (size_t)b * C_;
    __shared__ float sred[256];
    const int tid = threadIdx.x;

    float lmax = -3.4e38f;
    for (int i = tid; i < C_; i += 256) lmax = fmaxf(lmax, row[i]);
    sred[tid] = lmax;
    __syncthreads();
    for (int s = 128; s > 0; s >>= 1) {
        if (tid < s) sred[tid] = fmaxf(sred[tid], sred[tid + s]);
        __syncthreads();
    }
    const float mx = sred[0];
    __syncthreads();

    float lsum = 0.f;
    for (int i = tid; i < C_; i += 256) lsum += expf(row[i] - mx);
    sred[tid] = lsum;
    __syncthreads();
    for (int s = 128; s > 0; s >>= 1) {
        if (tid < s) sred[tid] += sred[tid + s];
        __syncthreads();
    }
    const float lse = mx + logf(sred[0]);

    for (int i = tid; i < C_; i += 256) row[i] = row[i] - lse;
}

// ---------------------------------------------------------------------------
#define SMEM_AH (5 * SA_H * 2 + 4 * BSTG_STAGE * 4 + 2 * B16_STAGE * 2)  // 115200
#define SMEM_AF (2 * SA_H * 2 + 4 * BSTG_STAGE * 4 + 2 * B16_STAGE * 2)  //  96768

extern "C" void kernel_launch(void* const* d_in, const int* in_sizes, int n_in,
                              void* d_out, int out_size)
{
    const float* x  = (const float*)d_in[0];
    const float* mf = (const float*)d_in[1];
    const float* W1 = (const float*)d_in[2];
    const float* b1 = (const float*)d_in[3];
    const float* W2 = (const float*)d_in[4];
    const float* b2 = (const float*)d_in[5];
    const float* W3 = (const float*)d_in[6];
    const float* b3 = (const float*)d_in[7];
    float* out = (float*)d_out;

    void *h1p = nullptr, *h2p = nullptr;
    cudaGetSymbolAddress(&h1p, g_h1);
    cudaGetSymbolAddress(&h2p, g_h2);

    cudaFuncSetAttribute(expert_gemm<true, false, true, true>,
                         cudaFuncAttributeMaxDynamicSharedMemorySize, SMEM_AF);
    cudaFuncSetAttribute(expert_gemm<true, true, true, true>,
                         cudaFuncAttributeMaxDynamicSharedMemorySize, SMEM_AH);
    cudaFuncSetAttribute(expert_gemm<false, true, false, false>,
                         cudaFuncAttributeMaxDynamicSharedMemorySize, SMEM_AH);

    route_kernel<<<1, B_>>>(mf);

    // L1: x fp32 [cnt,1536] @ W1 -> gelu -> h1 (fp16)
    expert_gemm<true, false, true, true>
        <<<dim3(H_ / BN, MT, E_), NTHREADS, SMEM_AF>>>(x, D_, W1, b1, h1p, H_, D_, H_);
    // L2: h1 fp16 [cnt,3072] @ W2 -> gelu -> h2 (fp16)
    expert_gemm<true, true, true, true>
        <<<dim3(H_ / BN, MT, E_), NTHREADS, SMEM_AH>>>(h1p, H_, W2, b2, h2p, H_, H_, H_);
    // L3: h2 fp16 [cnt,3072] @ W3 + b3 -> preds (fp32)
    expert_gemm<false, true, false, false>
        <<<dim3((C_ + BN - 1) / BN, MT, E_), NTHREADS, SMEM_AH>>>(h2p, H_, W3, b3, out, C_, H_, C_);
    logsoftmax_kernel<<<B_, 256>>>(out);
}